// round 10
// baseline (speedup 1.0000x reference)
#include <cuda_runtime.h>
#include <cuda_fp16.h>
#include <cstdint>

#define NB   64
#define TT   512
#define VV   25
#define CIN  3
#define CH   64
#define FF   25
#define G4   100   // 4*FF

typedef unsigned long long ull;

// Scratch (device globals — no allocation allowed)
__device__ __half g_zx_h[(size_t)NB * VV * TT * G4];   // 163.8 MB, layout (n,v,t,4f)
__device__ __half g_hs_h[(size_t)NB * TT * VV * FF];   // 41 MB, layout (n,t,v,f)
__device__ float  g_Wr[64 * 100];                      // reordered W_lstm
__device__ float  g_Wrs[64 * 100];                     // reordered, pair-swapped

__device__ __forceinline__ float hsig(float x) {
    return fminf(fmaxf(fmaf(0.2f, x, 0.5f), 0.0f), 1.0f);
}
__device__ __forceinline__ float tanh_fast(float x) {
    float y;
    asm("tanh.approx.f32 %0, %1;" : "=f"(y) : "f"(x));
    return y;
}

// ---- packed fp32x2 helpers (sm_103a) ----
__device__ __forceinline__ ull pk2(float lo, float hi) {
    ull r;
    asm("mov.b64 %0, {%1, %2};" : "=l"(r)
        : "r"(__float_as_uint(lo)), "r"(__float_as_uint(hi)));
    return r;
}
__device__ __forceinline__ void upk2(ull p, float& lo, float& hi) {
    unsigned int a, b;
    asm("mov.b64 {%0, %1}, %2;" : "=r"(a), "=r"(b) : "l"(p));
    lo = __uint_as_float(a); hi = __uint_as_float(b);
}
__device__ __forceinline__ ull fma2(ull a, ull b, ull c) {
    ull d;
    asm("fma.rn.f32x2 %0, %1, %2, %3;" : "=l"(d) : "l"(a), "l"(b), "l"(c));
    return d;
}
__device__ __forceinline__ ull add2(ull a, ull b) {
    ull d;
    asm("add.rn.f32x2 %0, %1, %2;" : "=l"(d) : "l"(a), "l"(b));
    return d;
}
__device__ __forceinline__ ull mul2(ull a, ull b) {
    ull d;
    asm("mul.rn.f32x2 %0, %1, %2;" : "=l"(d) : "l"(a), "l"(b));
    return d;
}

__device__ __forceinline__ uint2 pack_half4(float a, float b, float c, float d) {
    __half2 lo = __floats2half2_rn(a, b);
    __half2 hi = __floats2half2_rn(c, d);
    uint2 r;
    r.x = *reinterpret_cast<uint32_t*>(&lo);
    r.y = *reinterpret_cast<uint32_t*>(&hi);
    return r;
}

// ---------------------------------------------------------------------------
// K0: reorder W_lstm once.
//   Wr [k][4*f + kk] = Wl[k][kk*25 + f]
//   Wrs[k][j]        = Wr[k][j^1]        (pairs swapped within each 2-group)
// ---------------------------------------------------------------------------
__global__ void k0_reorder(const float* __restrict__ Wl) {
    int idx = blockIdx.x * 256 + threadIdx.x;
    if (idx < 6400) {
        int k = idx / 100, j = idx % 100;
        g_Wr[idx]  = Wl[k * 100 + (j & 3) * 25 + (j >> 2)];
        g_Wrs[idx] = Wl[k * 100 + ((j ^ 1) & 3) * 25 + (j >> 2)];
    }
}

// ---------------------------------------------------------------------------
// K1: zx = relu(x @ Wc + bc) @ Wl + bl  (gate-interleaved, fp16 out)
// 224 threads, tile 64 rows x 100 cols. Diagonal-pair FFMA2 main loop:
// u row-pairs (natural from LDS.128) x w col-pairs (natural + pre-swapped
// copy) -> 20 instr per k-iter (4 LDS + 16 fma2), zero packs.
// ---------------------------------------------------------------------------
__global__ void __launch_bounds__(224) k1_zx(const float* __restrict__ x,
                      const float* __restrict__ Wc,
                      const float* __restrict__ bc,
                      const float* __restrict__ bl) {
    __shared__ __align__(16) float xs[192];
    __shared__ float wcs[192];
    __shared__ float bcs[64];
    __shared__ __align__(16) float u_s[64 * 64];
    __shared__ __align__(16) float Ws[64 * 100];
    __shared__ __align__(16) float Wsw[64 * 100];

    const int tid  = threadIdx.x;
    const int row0 = blockIdx.x * 64;

    if (tid < 192) xs[tid]  = x[(size_t)row0 * 3 + tid];
    if (tid < 192) wcs[tid] = Wc[tid];
    if (tid < 64)  bcs[tid] = bc[tid];

    {
        const float4* s1 = reinterpret_cast<const float4*>(g_Wr);
        const float4* s2 = reinterpret_cast<const float4*>(g_Wrs);
        float4* d1 = reinterpret_cast<float4*>(Ws);
        float4* d2 = reinterpret_cast<float4*>(Wsw);
        for (int idx = tid; idx < 1600; idx += 224) { d1[idx] = s1[idx]; d2[idx] = s2[idx]; }
    }
    __syncthreads();

    for (int idx = tid; idx < 4096; idx += 224) {
        int ch = idx >> 6, r = idx & 63;
        float v = fmaf(xs[r * 3 + 2], wcs[128 + ch],
                  fmaf(xs[r * 3 + 1], wcs[64 + ch],
                  fmaf(xs[r * 3 + 0], wcs[ch], bcs[ch])));
        u_s[ch * 64 + r] = fmaxf(v, 0.0f);
    }
    __syncthreads();

    const int w    = tid >> 5;
    const int lane = tid & 31;
    const int n    = blockIdx.x / 200;          // 12800 rows per n, 64 per block
    const int remb = (blockIdx.x % 200) * 64;   // row offset within (t,v) plane

    if (w < 6) {
        const int rt  = lane >> 2;            // rows rt*8 .. rt*8+7 (4 pairs)
        const int ct4 = w * 4 + (lane & 3);   // cols 4*ct4 .. 4*ct4+3

        const float b0 = bl[ct4], b1 = bl[25 + ct4], b2 = bl[50 + ct4], b3 = bl[75 + ct4];
        // d0[p][q]: (r_even*c_even, r_odd*c_odd) diag; d1: cross diag
        ull d0[4][2], d1[4][2];
#pragma unroll
        for (int p = 0; p < 4; p++) {
            d0[p][0] = pk2(b0, b1); d1[p][0] = pk2(b1, b0);
            d0[p][1] = pk2(b2, b3); d1[p][1] = pk2(b3, b2);
        }

#pragma unroll 8
        for (int k = 0; k < 64; k++) {
            ulonglong2 wp  = *reinterpret_cast<const ulonglong2*>(&Ws[k * 100 + 4 * ct4]);
            ulonglong2 wps = *reinterpret_cast<const ulonglong2*>(&Wsw[k * 100 + 4 * ct4]);
            ulonglong2 uA  = *reinterpret_cast<const ulonglong2*>(&u_s[k * 64 + 8 * rt]);
            ulonglong2 uB  = *reinterpret_cast<const ulonglong2*>(&u_s[k * 64 + 8 * rt + 4]);
            ull up[4] = {uA.x, uA.y, uB.x, uB.y};
#pragma unroll
            for (int p = 0; p < 4; p++) {
                d0[p][0] = fma2(up[p], wp.x,  d0[p][0]);
                d1[p][0] = fma2(up[p], wps.x, d1[p][0]);
                d0[p][1] = fma2(up[p], wp.y,  d0[p][1]);
                d1[p][1] = fma2(up[p], wps.y, d1[p][1]);
            }
        }

#pragma unroll
        for (int p = 0; p < 4; p++) {
            int rem = remb + rt * 8 + 2 * p;      // even row
            float a0lo, a0hi, b0lo, b0hi, a1lo, a1hi, b1lo, b1hi;
            upk2(d0[p][0], a0lo, a0hi);   // (r0c0, r1c1)
            upk2(d1[p][0], b0lo, b0hi);   // (r0c1, r1c0)
            upk2(d0[p][1], a1lo, a1hi);   // (r0c2, r1c3)
            upk2(d1[p][1], b1lo, b1hi);   // (r0c3, r1c2)
            {
                int t = rem / VV, v = rem - t * VV;
                size_t zo = (((size_t)(n * VV + v)) * TT + t) * G4 + 4 * ct4;
                *reinterpret_cast<uint2*>(&g_zx_h[zo]) = pack_half4(a0lo, b0lo, a1lo, b1lo);
            }
            {
                int rem1 = rem + 1;
                int t = rem1 / VV, v = rem1 - t * VV;
                size_t zo = (((size_t)(n * VV + v)) * TT + t) * G4 + 4 * ct4;
                *reinterpret_cast<uint2*>(&g_zx_h[zo]) = pack_half4(b0hi, a0hi, b1hi, a1hi);
            }
        }
    } else {
        // edge warp: cols 96..99 (feature 24), rows lane and lane+32
        ull bA = pk2(bl[24], bl[49]);
        ull bB = pk2(bl[74], bl[99]);
        ull aA01 = bA, aA23 = bB, aB01 = bA, aB23 = bB;
#pragma unroll 8
        for (int k = 0; k < 64; k++) {
            ulonglong2 wp = *reinterpret_cast<const ulonglong2*>(&Ws[k * 100 + 96]);
            float uaa = u_s[k * 64 + lane];
            float ubb = u_s[k * 64 + 32 + lane];
            ull uA = pk2(uaa, uaa);
            ull uB = pk2(ubb, ubb);
            aA01 = fma2(uA, wp.x, aA01); aA23 = fma2(uA, wp.y, aA23);
            aB01 = fma2(uB, wp.x, aB01); aB23 = fma2(uB, wp.y, aB23);
        }
#pragma unroll
        for (int h2 = 0; h2 < 2; h2++) {
            int rem = remb + lane + 32 * h2;
            int t = rem / VV, v = rem - t * VV;
            size_t zo = (((size_t)(n * VV + v)) * TT + t) * G4 + 96;
            float g0, g1, g2, g3;
            if (h2 == 0) { upk2(aA01, g0, g1); upk2(aA23, g2, g3); }
            else         { upk2(aB01, g0, g1); upk2(aB23, g2, g3); }
            *reinterpret_cast<uint2*>(&g_zx_h[zo]) = pack_half4(g0, g1, g2, g3);
        }
    }
}

// ---------------------------------------------------------------------------
// K2: LSTM recurrence. One warp per (n,v) sequence. f32x2 gate pairs,
// HW tanh.approx, fp16 zx in / fp16 hs out.
// ---------------------------------------------------------------------------
__global__ void __launch_bounds__(32, 12) k2_lstm(const float* __restrict__ U) {
    const int l = threadIdx.x & 31;
    const int s = blockIdx.x;
    const int n = s / VV, v = s % VV;
    const int li = (l < 25) ? l : 0;

    ull Uif[25], Ugo[25];
#pragma unroll
    for (int f = 0; f < 25; f++) {
        Uif[f] = pk2(U[f * 100 + li],      U[f * 100 + 25 + li]);
        Ugo[f] = pk2(U[f * 100 + 50 + li], U[f * 100 + 75 + li]);
    }

    const uint2* zp = reinterpret_cast<const uint2*>(g_zx_h + (size_t)s * TT * G4);
    uint2 z0 = zp[li];
    uint2 z1 = zp[25 + li];

    float c = 0.0f, h = 0.0f;
    __half* hout = g_hs_h + ((size_t)n * TT * VV + v) * FF + li;

    for (int t = 0; t < TT; t++) {
        uint2 zc = z0;
        z0 = z1;
        int tn = (t + 2 < TT) ? (t + 2) : (TT - 1);
        z1 = zp[(size_t)tn * 25 + li];

        ull aIF0 = 0, aIF1 = 0, aIF2 = 0, aIF3 = 0;
        ull aGO0 = 0, aGO1 = 0, aGO2 = 0, aGO3 = 0;
#pragma unroll
        for (int f = 0; f < 24; f += 4) {
            float h0 = __shfl_sync(0xffffffffu, h, f);
            float h1 = __shfl_sync(0xffffffffu, h, f + 1);
            float h2 = __shfl_sync(0xffffffffu, h, f + 2);
            float h3 = __shfl_sync(0xffffffffu, h, f + 3);
            ull hh0 = pk2(h0, h0), hh1 = pk2(h1, h1);
            ull hh2 = pk2(h2, h2), hh3 = pk2(h3, h3);
            aIF0 = fma2(hh0, Uif[f],     aIF0); aGO0 = fma2(hh0, Ugo[f],     aGO0);
            aIF1 = fma2(hh1, Uif[f + 1], aIF1); aGO1 = fma2(hh1, Ugo[f + 1], aGO1);
            aIF2 = fma2(hh2, Uif[f + 2], aIF2); aGO2 = fma2(hh2, Ugo[f + 2], aGO2);
            aIF3 = fma2(hh3, Uif[f + 3], aIF3); aGO3 = fma2(hh3, Ugo[f + 3], aGO3);
        }
        {
            float h0 = __shfl_sync(0xffffffffu, h, 24);
            ull hh0 = pk2(h0, h0);
            aIF0 = fma2(hh0, Uif[24], aIF0);
            aGO0 = fma2(hh0, Ugo[24], aGO0);
        }

        __half2 hlo = *reinterpret_cast<__half2*>(&zc.x);
        __half2 hhi = *reinterpret_cast<__half2*>(&zc.y);
        float2 f01 = __half22float2(hlo);
        float2 f23 = __half22float2(hhi);

        ull sIF = add2(add2(aIF0, aIF1), add2(aIF2, aIF3));
        ull sGO = add2(add2(aGO0, aGO1), add2(aGO2, aGO3));
        sIF = add2(sIF, pk2(f01.x, f01.y));
        sGO = add2(sGO, pk2(f23.x, f23.y));

        float gi, gf, gg, go;
        upk2(sIF, gi, gf);
        upk2(sGO, gg, go);

        c = fmaf(hsig(gf), c, hsig(gi) * tanh_fast(gg));
        h = hsig(go) * tanh_fast(c);

        if (l < 25) hout[(size_t)t * (VV * FF)] = __float2half_rn(h);
    }
}

// ---------------------------------------------------------------------------
// K3: block = 160 threads = 2 tiles x 80. exp directly into duplicated f32x2
// es2 (no raw array), in-place row normalization, x1 recompute, 5v x 4c GEMM.
// smem ~25.7KB -> 8 blocks/SM.
// ---------------------------------------------------------------------------
__global__ void __launch_bounds__(160) k3_out(const float* __restrict__ x,
                       const float* __restrict__ Wc,
                       const float* __restrict__ bc,
                       const float* __restrict__ bias,
                       float* __restrict__ out) {
    __shared__ float wcs[192];
    __shared__ float bcs[64];
    __shared__ float xs[2][80];
    __shared__ __align__(16) float x1s[2][25 * 68];
    __shared__ __align__(16) ull es2[2][25 * 26];

    const int tid  = threadIdx.x;
    const int half = (tid >= 80) ? 1 : 0;
    const int t2   = tid - 80 * half;
    const size_t nt = (size_t)blockIdx.x * 2 + half;

    for (int i = tid; i < 192; i += 160) wcs[i] = Wc[i];
    if (tid >= 96 && tid < 160) bcs[tid - 96] = bc[tid - 96];
    if (t2 < 75) xs[half][t2] = x[nt * 75 + t2];

    const __half* hp = g_hs_h + nt * 625;
    for (int idx = t2; idx < 625; idx += 80) {
        float hv = __half2float(hp[idx]);
        float lv = (hv > 0.0f) ? hv : 0.2f * hv;
        float e  = __expf(lv + __ldg(bias + idx));
        es2[half][(idx / 25) * 26 + (idx % 25)] = pk2(e, e);
    }
    __syncthreads();

    if (t2 < 25) {
        const float* elo = reinterpret_cast<const float*>(&es2[half][t2 * 26]);
        float sum = 0.0f;
#pragma unroll
        for (int w2 = 0; w2 < 25; w2++) sum += elo[2 * w2];
        ull ii = pk2(1.0f / sum, 1.0f / sum);
#pragma unroll
        for (int w2 = 0; w2 < 25; w2++)
            es2[half][t2 * 26 + w2] = mul2(es2[half][t2 * 26 + w2], ii);
    }
    for (int idx = t2; idx < 1600; idx += 80) {
        int wj = idx >> 6, cc = idx & 63;
        float u = fmaf(xs[half][wj * 3 + 2], wcs[128 + cc],
                  fmaf(xs[half][wj * 3 + 1], wcs[64 + cc],
                  fmaf(xs[half][wj * 3 + 0], wcs[cc], bcs[cc])));
        x1s[half][wj * 68 + cc] = fmaxf(u, 0.0f);
    }
    __syncthreads();

    {
        const int vg = t2 / 16;
        const int cg = t2 % 16;

        ull a01[5] = {0, 0, 0, 0, 0};
        ull a23[5] = {0, 0, 0, 0, 0};
        const ull* e2 = &es2[half][0];
#pragma unroll
        for (int w2 = 0; w2 < 25; w2++) {
            ulonglong2 xp = *reinterpret_cast<const ulonglong2*>(&x1s[half][w2 * 68 + 4 * cg]);
#pragma unroll
            for (int j = 0; j < 5; j++) {
                ull ee = e2[(vg * 5 + j) * 26 + w2];
                a01[j] = fma2(ee, xp.x, a01[j]);
                a23[j] = fma2(ee, xp.y, a23[j]);
            }
        }

        float* op = out + nt * 1600;
#pragma unroll
        for (int j = 0; j < 5; j++) {
            int vv = vg * 5 + j;
            ulonglong2 o;
            o.x = a01[j];
            o.y = a23[j];
            *reinterpret_cast<ulonglong2*>(&op[vv * 64 + 4 * cg]) = o;
        }
    }
}

extern "C" void kernel_launch(void* const* d_in, const int* in_sizes, int n_in,
                              void* d_out, int out_size) {
    const float* x    = (const float*)d_in[0];
    const float* Wc   = (const float*)d_in[1];
    const float* bc   = (const float*)d_in[2];
    const float* Wl   = (const float*)d_in[3];
    const float* Ul   = (const float*)d_in[4];
    const float* bl   = (const float*)d_in[5];
    const float* bias = (const float*)d_in[6];
    float* out = (float*)d_out;

    k0_reorder<<<25, 256>>>(Wl);
    k1_zx<<<12800, 224>>>(x, Wc, bc, bl);
    k2_lstm<<<1600, 32>>>(Ul);
    k3_out<<<16384, 160>>>(x, Wc, bc, bias, out);
}

// round 11
// speedup vs baseline: 1.2464x; 1.2464x over previous
#include <cuda_runtime.h>
#include <cuda_fp16.h>
#include <cstdint>

#define NB   64
#define TT   512
#define VV   25
#define CIN  3
#define CH   64
#define FF   25
#define G4   100   // 4*FF

typedef unsigned long long ull;

// Scratch (device globals — no allocation allowed)
__device__ __half g_zx_h[(size_t)NB * VV * TT * G4];   // 163.8 MB, layout (n,v,t,4f)
__device__ __half g_hs_h[(size_t)NB * TT * VV * FF];   // 41 MB, layout (n,t,v,f)
__device__ float  g_Wr[64 * 100];                      // reordered W_lstm

__device__ __forceinline__ float hsig(float x) {
    return fminf(fmaxf(fmaf(0.2f, x, 0.5f), 0.0f), 1.0f);
}
__device__ __forceinline__ float tanh_fast(float x) {
    float y;
    asm("tanh.approx.f32 %0, %1;" : "=f"(y) : "f"(x));
    return y;
}

// ---- packed fp32x2 helpers (sm_103a) ----
__device__ __forceinline__ ull pk2(float lo, float hi) {
    ull r;
    asm("mov.b64 %0, {%1, %2};" : "=l"(r)
        : "r"(__float_as_uint(lo)), "r"(__float_as_uint(hi)));
    return r;
}
__device__ __forceinline__ void upk2(ull p, float& lo, float& hi) {
    unsigned int a, b;
    asm("mov.b64 {%0, %1}, %2;" : "=r"(a), "=r"(b) : "l"(p));
    lo = __uint_as_float(a); hi = __uint_as_float(b);
}
__device__ __forceinline__ ull swap64(ull p) {
    unsigned int a, b;
    asm("mov.b64 {%0, %1}, %2;" : "=r"(a), "=r"(b) : "l"(p));
    ull r;
    asm("mov.b64 %0, {%1, %2};" : "=l"(r) : "r"(b), "r"(a));
    return r;
}
__device__ __forceinline__ ull fma2(ull a, ull b, ull c) {
    ull d;
    asm("fma.rn.f32x2 %0, %1, %2, %3;" : "=l"(d) : "l"(a), "l"(b), "l"(c));
    return d;
}
__device__ __forceinline__ ull add2(ull a, ull b) {
    ull d;
    asm("add.rn.f32x2 %0, %1, %2;" : "=l"(d) : "l"(a), "l"(b));
    return d;
}

__device__ __forceinline__ uint2 pack_half4(float a, float b, float c, float d) {
    __half2 lo = __floats2half2_rn(a, b);
    __half2 hi = __floats2half2_rn(c, d);
    uint2 r;
    r.x = *reinterpret_cast<uint32_t*>(&lo);
    r.y = *reinterpret_cast<uint32_t*>(&hi);
    return r;
}

// ---------------------------------------------------------------------------
// K0: reorder W_lstm once: Wr[k][4*f + kk] = Wl[k][kk*25 + f]
// ---------------------------------------------------------------------------
__global__ void k0_reorder(const float* __restrict__ Wl) {
    int idx = blockIdx.x * 256 + threadIdx.x;
    if (idx < 6400) {
        int k = idx / 100, j = idx % 100;
        g_Wr[idx] = Wl[k * 100 + (j & 3) * 25 + (j >> 2)];
    }
}

// ---------------------------------------------------------------------------
// K1: zx = relu(x @ Wc + bc) @ Wl + bl  (gate-interleaved, fp16 out)
// 224 threads, tile 64 rows x 100 cols. Diagonal-pair FFMA2 with u-swap in
// registers (no second W copy -> smem unchanged, 5 blocks/SM):
//   d0 += (u_e,u_o)*(w_e,w_o) = (r_e*c_e, r_o*c_o)
//   d1 += (u_o,u_e)*(w_e,w_o) = (r_o*c_e, r_e*c_o)
// Per k-iter: 3 LDS.128 + 4 swap64 + 16 fma2.
// ---------------------------------------------------------------------------
__global__ void __launch_bounds__(224) k1_zx(const float* __restrict__ x,
                      const float* __restrict__ Wc,
                      const float* __restrict__ bc,
                      const float* __restrict__ bl) {
    __shared__ __align__(16) float xs[192];
    __shared__ float wcs[192];
    __shared__ float bcs[64];
    __shared__ __align__(16) float u_s[64 * 64];
    __shared__ __align__(16) float Ws[64 * 100];

    const int tid  = threadIdx.x;
    const int row0 = blockIdx.x * 64;

    if (tid < 192) xs[tid]  = x[(size_t)row0 * 3 + tid];
    if (tid < 192) wcs[tid] = Wc[tid];
    if (tid < 64)  bcs[tid] = bc[tid];

    {
        const float4* src = reinterpret_cast<const float4*>(g_Wr);
        float4* dst = reinterpret_cast<float4*>(Ws);
        for (int idx = tid; idx < 1600; idx += 224) dst[idx] = src[idx];
    }
    __syncthreads();

    for (int idx = tid; idx < 4096; idx += 224) {
        int ch = idx >> 6, r = idx & 63;
        float v = fmaf(xs[r * 3 + 2], wcs[128 + ch],
                  fmaf(xs[r * 3 + 1], wcs[64 + ch],
                  fmaf(xs[r * 3 + 0], wcs[ch], bcs[ch])));
        u_s[ch * 64 + r] = fmaxf(v, 0.0f);
    }
    __syncthreads();

    const int w    = tid >> 5;
    const int lane = tid & 31;
    const int n    = blockIdx.x / 200;          // 12800 rows per n, 64 per block
    const int remb = (blockIdx.x % 200) * 64;   // row offset within (t,v) plane

    if (w < 6) {
        const int rt  = lane >> 2;            // rows rt*8 .. rt*8+7 (4 pairs)
        const int ct4 = w * 4 + (lane & 3);   // cols 4*ct4 .. 4*ct4+3

        const float b0 = bl[ct4], b1 = bl[25 + ct4], b2 = bl[50 + ct4], b3 = bl[75 + ct4];
        // d0[p][q] holds (r_even*c_even, r_odd*c_odd); d1[p][q] holds
        // (r_odd*c_even, r_even*c_odd). Each output element appears once,
        // so both diagonals initialize with (b_ceven, b_codd).
        ull d0[4][2], d1[4][2];
#pragma unroll
        for (int p = 0; p < 4; p++) {
            d0[p][0] = pk2(b0, b1); d1[p][0] = pk2(b0, b1);
            d0[p][1] = pk2(b2, b3); d1[p][1] = pk2(b2, b3);
        }

#pragma unroll 8
        for (int k = 0; k < 64; k++) {
            ulonglong2 wp = *reinterpret_cast<const ulonglong2*>(&Ws[k * 100 + 4 * ct4]);
            ulonglong2 uA = *reinterpret_cast<const ulonglong2*>(&u_s[k * 64 + 8 * rt]);
            ulonglong2 uB = *reinterpret_cast<const ulonglong2*>(&u_s[k * 64 + 8 * rt + 4]);
            ull up[4] = {uA.x, uA.y, uB.x, uB.y};
#pragma unroll
            for (int p = 0; p < 4; p++) {
                ull us = swap64(up[p]);
                d0[p][0] = fma2(up[p], wp.x, d0[p][0]);
                d1[p][0] = fma2(us,    wp.x, d1[p][0]);
                d0[p][1] = fma2(up[p], wp.y, d0[p][1]);
                d1[p][1] = fma2(us,    wp.y, d1[p][1]);
            }
        }

#pragma unroll
        for (int p = 0; p < 4; p++) {
            int rem = remb + rt * 8 + 2 * p;      // even row
            float a0lo, a0hi, b0lo, b0hi, a1lo, a1hi, b1lo, b1hi;
            upk2(d0[p][0], a0lo, a0hi);   // (r0c0, r1c1)
            upk2(d1[p][0], b0lo, b0hi);   // (r1c0, r0c1)
            upk2(d0[p][1], a1lo, a1hi);   // (r0c2, r1c3)
            upk2(d1[p][1], b1lo, b1hi);   // (r1c2, r0c3)
            {   // even row: c0=a0lo, c1=b0hi, c2=a1lo, c3=b1hi
                int t = rem / VV, v = rem - t * VV;
                size_t zo = (((size_t)(n * VV + v)) * TT + t) * G4 + 4 * ct4;
                *reinterpret_cast<uint2*>(&g_zx_h[zo]) = pack_half4(a0lo, b0hi, a1lo, b1hi);
            }
            {   // odd row: c0=b0lo, c1=a0hi, c2=b1lo, c3=a1hi
                int rem1 = rem + 1;
                int t = rem1 / VV, v = rem1 - t * VV;
                size_t zo = (((size_t)(n * VV + v)) * TT + t) * G4 + 4 * ct4;
                *reinterpret_cast<uint2*>(&g_zx_h[zo]) = pack_half4(b0lo, a0hi, b1lo, a1hi);
            }
        }
    } else {
        // edge warp: cols 96..99 (feature 24), rows lane and lane+32
        ull bA = pk2(bl[24], bl[49]);
        ull bB = pk2(bl[74], bl[99]);
        ull aA01 = bA, aA23 = bB, aB01 = bA, aB23 = bB;
#pragma unroll 8
        for (int k = 0; k < 64; k++) {
            ulonglong2 wp = *reinterpret_cast<const ulonglong2*>(&Ws[k * 100 + 96]);
            float uaa = u_s[k * 64 + lane];
            float ubb = u_s[k * 64 + 32 + lane];
            ull uA = pk2(uaa, uaa);
            ull uB = pk2(ubb, ubb);
            aA01 = fma2(uA, wp.x, aA01); aA23 = fma2(uA, wp.y, aA23);
            aB01 = fma2(uB, wp.x, aB01); aB23 = fma2(uB, wp.y, aB23);
        }
#pragma unroll
        for (int h2 = 0; h2 < 2; h2++) {
            int rem = remb + lane + 32 * h2;
            int t = rem / VV, v = rem - t * VV;
            size_t zo = (((size_t)(n * VV + v)) * TT + t) * G4 + 96;
            float g0, g1, g2, g3;
            if (h2 == 0) { upk2(aA01, g0, g1); upk2(aA23, g2, g3); }
            else         { upk2(aB01, g0, g1); upk2(aB23, g2, g3); }
            *reinterpret_cast<uint2*>(&g_zx_h[zo]) = pack_half4(g0, g1, g2, g3);
        }
    }
}

// ---------------------------------------------------------------------------
// K2: LSTM recurrence. One warp per (n,v) sequence. f32x2 gate pairs,
// HW tanh.approx, fp16 zx in / fp16 hs out.  (identical to R7)
// ---------------------------------------------------------------------------
__global__ void __launch_bounds__(32, 12) k2_lstm(const float* __restrict__ U) {
    const int l = threadIdx.x & 31;
    const int s = blockIdx.x;
    const int n = s / VV, v = s % VV;
    const int li = (l < 25) ? l : 0;

    ull Uif[25], Ugo[25];
#pragma unroll
    for (int f = 0; f < 25; f++) {
        Uif[f] = pk2(U[f * 100 + li],      U[f * 100 + 25 + li]);
        Ugo[f] = pk2(U[f * 100 + 50 + li], U[f * 100 + 75 + li]);
    }

    const uint2* zp = reinterpret_cast<const uint2*>(g_zx_h + (size_t)s * TT * G4);
    uint2 z0 = zp[li];
    uint2 z1 = zp[25 + li];

    float c = 0.0f, h = 0.0f;
    __half* hout = g_hs_h + ((size_t)n * TT * VV + v) * FF + li;

    for (int t = 0; t < TT; t++) {
        uint2 zc = z0;
        z0 = z1;
        int tn = (t + 2 < TT) ? (t + 2) : (TT - 1);
        z1 = zp[(size_t)tn * 25 + li];

        ull aIF0 = 0, aIF1 = 0, aIF2 = 0, aIF3 = 0;
        ull aGO0 = 0, aGO1 = 0, aGO2 = 0, aGO3 = 0;
#pragma unroll
        for (int f = 0; f < 24; f += 4) {
            float h0 = __shfl_sync(0xffffffffu, h, f);
            float h1 = __shfl_sync(0xffffffffu, h, f + 1);
            float h2 = __shfl_sync(0xffffffffu, h, f + 2);
            float h3 = __shfl_sync(0xffffffffu, h, f + 3);
            ull hh0 = pk2(h0, h0), hh1 = pk2(h1, h1);
            ull hh2 = pk2(h2, h2), hh3 = pk2(h3, h3);
            aIF0 = fma2(hh0, Uif[f],     aIF0); aGO0 = fma2(hh0, Ugo[f],     aGO0);
            aIF1 = fma2(hh1, Uif[f + 1], aIF1); aGO1 = fma2(hh1, Ugo[f + 1], aGO1);
            aIF2 = fma2(hh2, Uif[f + 2], aIF2); aGO2 = fma2(hh2, Ugo[f + 2], aGO2);
            aIF3 = fma2(hh3, Uif[f + 3], aIF3); aGO3 = fma2(hh3, Ugo[f + 3], aGO3);
        }
        {
            float h0 = __shfl_sync(0xffffffffu, h, 24);
            ull hh0 = pk2(h0, h0);
            aIF0 = fma2(hh0, Uif[24], aIF0);
            aGO0 = fma2(hh0, Ugo[24], aGO0);
        }

        __half2 hlo = *reinterpret_cast<__half2*>(&zc.x);
        __half2 hhi = *reinterpret_cast<__half2*>(&zc.y);
        float2 f01 = __half22float2(hlo);
        float2 f23 = __half22float2(hhi);

        ull sIF = add2(add2(aIF0, aIF1), add2(aIF2, aIF3));
        ull sGO = add2(add2(aGO0, aGO1), add2(aGO2, aGO3));
        sIF = add2(sIF, pk2(f01.x, f01.y));
        sGO = add2(sGO, pk2(f23.x, f23.y));

        float gi, gf, gg, go;
        upk2(sIF, gi, gf);
        upk2(sGO, gg, go);

        c = fmaf(hsig(gf), c, hsig(gi) * tanh_fast(gg));
        h = hsig(go) * tanh_fast(c);

        if (l < 25) hout[(size_t)t * (VV * FF)] = __float2half_rn(h);
    }
}

// ---------------------------------------------------------------------------
// K3: block = 160 threads = 2 tiles x 80. Per tile: exp(leaky(h)+bias),
// fold 1/rowsum into es (duplicated f32x2), x1 recompute, 5v x 4c GEMM.
// (identical to R7 — 58 regs, 7 blocks/SM)
// ---------------------------------------------------------------------------
__global__ void __launch_bounds__(160) k3_out(const float* __restrict__ x,
                       const float* __restrict__ Wc,
                       const float* __restrict__ bc,
                       const float* __restrict__ bias,
                       float* __restrict__ out) {
    __shared__ float wcs[192];
    __shared__ float bcs[64];
    __shared__ float esr[2][25 * 26];
    __shared__ float xs[2][80];
    __shared__ __align__(16) float x1s[2][25 * 68];
    __shared__ __align__(16) ull es2[2][25 * 26];

    const int tid  = threadIdx.x;
    const int half = (tid >= 80) ? 1 : 0;
    const int t2   = tid - 80 * half;
    const size_t nt = (size_t)blockIdx.x * 2 + half;

    for (int i = tid; i < 192; i += 160) wcs[i] = Wc[i];
    if (tid >= 96 && tid < 160) bcs[tid - 96] = bc[tid - 96];
    if (t2 < 75) xs[half][t2] = x[nt * 75 + t2];

    const __half* hp = g_hs_h + nt * 625;
    for (int idx = t2; idx < 625; idx += 80) {
        float hv = __half2float(hp[idx]);
        float lv = (hv > 0.0f) ? hv : 0.2f * hv;
        esr[half][(idx / 25) * 26 + (idx % 25)] = __expf(lv + __ldg(bias + idx));
    }
    __syncthreads();

    if (t2 < 25) {
        float sum = 0.0f;
#pragma unroll
        for (int w2 = 0; w2 < 25; w2++) sum += esr[half][t2 * 26 + w2];
        float inv = 1.0f / sum;
#pragma unroll
        for (int w2 = 0; w2 < 25; w2++) {
            float e = esr[half][t2 * 26 + w2] * inv;
            es2[half][t2 * 26 + w2] = pk2(e, e);
        }
    }
    for (int idx = t2; idx < 1600; idx += 80) {
        int wj = idx >> 6, cc = idx & 63;
        float u = fmaf(xs[half][wj * 3 + 2], wcs[128 + cc],
                  fmaf(xs[half][wj * 3 + 1], wcs[64 + cc],
                  fmaf(xs[half][wj * 3 + 0], wcs[cc], bcs[cc])));
        x1s[half][wj * 68 + cc] = fmaxf(u, 0.0f);
    }
    __syncthreads();

    {
        const int vg = t2 / 16;
        const int cg = t2 % 16;

        ull a01[5] = {0, 0, 0, 0, 0};
        ull a23[5] = {0, 0, 0, 0, 0};
        const ull* e2 = &es2[half][0];
#pragma unroll
        for (int w2 = 0; w2 < 25; w2++) {
            ulonglong2 xp = *reinterpret_cast<const ulonglong2*>(&x1s[half][w2 * 68 + 4 * cg]);
#pragma unroll
            for (int j = 0; j < 5; j++) {
                ull ee = e2[(vg * 5 + j) * 26 + w2];
                a01[j] = fma2(ee, xp.x, a01[j]);
                a23[j] = fma2(ee, xp.y, a23[j]);
            }
        }

        float* op = out + nt * 1600;
#pragma unroll
        for (int j = 0; j < 5; j++) {
            int vv = vg * 5 + j;
            ulonglong2 o;
            o.x = a01[j];
            o.y = a23[j];
            *reinterpret_cast<ulonglong2*>(&op[vv * 64 + 4 * cg]) = o;
        }
    }
}

extern "C" void kernel_launch(void* const* d_in, const int* in_sizes, int n_in,
                              void* d_out, int out_size) {
    const float* x    = (const float*)d_in[0];
    const float* Wc   = (const float*)d_in[1];
    const float* bc   = (const float*)d_in[2];
    const float* Wl   = (const float*)d_in[3];
    const float* Ul   = (const float*)d_in[4];
    const float* bl   = (const float*)d_in[5];
    const float* bias = (const float*)d_in[6];
    float* out = (float*)d_out;

    k0_reorder<<<25, 256>>>(Wl);
    k1_zx<<<12800, 224>>>(x, Wc, bc, bl);
    k2_lstm<<<1600, 32>>>(Ul);
    k3_out<<<16384, 160>>>(x, Wc, bc, bias, out);
}

// round 17
// speedup vs baseline: 1.7073x; 1.3698x over previous
#include <cuda_runtime.h>
#include <cuda_fp16.h>
#include <cstdint>

#define NB   64
#define TT   512
#define VV   25
#define CIN  3
#define CH   64
#define FF   25
#define G4   100   // 4*FF

typedef unsigned long long ull;

// Scratch (device globals — no allocation allowed)
__device__ __half g_zx_h[(size_t)NB * VV * TT * G4];   // 163.8 MB, layout (n,v,t,4f)
__device__ __half g_hs_h[(size_t)NB * TT * VV * FF];   // 41 MB, layout (n,t,v,f)
// B fragments for mma.sync m16n8k16 (fragment-order, fp16):
// index [(ks*13 + nt)*32 + lane] -> uint2 {b0 = (k,k+1 | n), b1 = (k+8,k+9 | n)}
// with k = 16*ks + 2*(lane&3), n = 8*nt + (lane>>2), B[k][n] = Wl[k][orig(n)]
__device__ uint2 g_Bfrag[4 * 13 * 32];

__device__ __forceinline__ float hsig(float x) {
    return fminf(fmaxf(fmaf(0.2f, x, 0.5f), 0.0f), 1.0f);
}
__device__ __forceinline__ float tanh_fast(float x) {
    float y;
    asm("tanh.approx.f32 %0, %1;" : "=f"(y) : "f"(x));
    return y;
}

// ---- packed fp32x2 helpers ----
__device__ __forceinline__ ull pk2(float lo, float hi) {
    ull r;
    asm("mov.b64 %0, {%1, %2};" : "=l"(r)
        : "r"(__float_as_uint(lo)), "r"(__float_as_uint(hi)));
    return r;
}
__device__ __forceinline__ void upk2(ull p, float& lo, float& hi) {
    unsigned int a, b;
    asm("mov.b64 {%0, %1}, %2;" : "=r"(a), "=r"(b) : "l"(p));
    lo = __uint_as_float(a); hi = __uint_as_float(b);
}
__device__ __forceinline__ ull fma2(ull a, ull b, ull c) {
    ull d;
    asm("fma.rn.f32x2 %0, %1, %2, %3;" : "=l"(d) : "l"(a), "l"(b), "l"(c));
    return d;
}
__device__ __forceinline__ ull add2(ull a, ull b) {
    ull d;
    asm("add.rn.f32x2 %0, %1, %2;" : "=l"(d) : "l"(a), "l"(b));
    return d;
}

__device__ __forceinline__ uint32_t pack_h2(float a, float b) {
    __half2 h = __floats2half2_rn(a, b);
    return *reinterpret_cast<uint32_t*>(&h);
}

// ---------------------------------------------------------------------------
// K0: bake B fragments. orig(n) = (n&3)*25 + (n>>2); n >= 100 -> 0.
// ---------------------------------------------------------------------------
__global__ void k0_prep(const float* __restrict__ Wl) {
    int idx = blockIdx.x * 256 + threadIdx.x;
    if (idx < 4 * 13 * 32) {
        int lane = idx & 31;
        int nt   = (idx >> 5) % 13;
        int ks   = idx / (13 * 32);
        int gid  = lane >> 2, tig = lane & 3;
        int n8 = 8 * nt + gid;
        int k  = 16 * ks + 2 * tig;

        float w0 = 0.f, w1 = 0.f, w8 = 0.f, w9 = 0.f;
        if (n8 < 100) {
            int oc = (n8 & 3) * 25 + (n8 >> 2);
            w0 = Wl[(k    ) * 100 + oc];
            w1 = Wl[(k + 1) * 100 + oc];
            w8 = Wl[(k + 8) * 100 + oc];
            w9 = Wl[(k + 9) * 100 + oc];
        }
        uint2 b;
        b.x = pack_h2(w0, w1);
        b.y = pack_h2(w8, w9);
        g_Bfrag[idx] = b;
    }
}

// ---------------------------------------------------------------------------
// K1: zx = relu(x @ Wc + bc) @ Wl  (bias folded into K2), fp16 out.
// mma.sync m16n8k16 fp16: block = 128 thr = 4 warps, M=64 rows/block,
// warp strip m16 x (N=104 in 13 n-tiles) x K=64 (4 k-steps) = 52 HMMA.
// A fragments computed directly in registers (3-FMA conv + relu + cvt).
// ---------------------------------------------------------------------------
__global__ void __launch_bounds__(128) k1_zx_mma(const float* __restrict__ x,
                       const float* __restrict__ Wc,
                       const float* __restrict__ bc) {
    __shared__ __align__(16) float xs[192];   // 64 rows x 3
    __shared__ float wcs[192];
    __shared__ float bcs[64];

    const int tid  = threadIdx.x;
    const int w    = tid >> 5;
    const int lane = tid & 31;
    const int gid  = lane >> 2;
    const int tig  = lane & 3;
    const int n    = blockIdx.x / 200;
    const int remb = (blockIdx.x % 200) * 64;
    const size_t row0 = (size_t)blockIdx.x * 64;

    {
        int i = tid;
        xs[i] = x[row0 * 3 + i];
        xs[i + 128 < 192 ? i + 128 : i] = x[row0 * 3 + (i + 128 < 192 ? i + 128 : i)];
        wcs[i] = Wc[i];
        if (i + 128 < 192) wcs[i + 128] = Wc[i + 128];
        if (i < 64) bcs[i] = bc[i];
    }
    __syncthreads();

    const int r0l = 16 * w + gid;       // local row (a0/a2 row)
    const int r1l = r0l + 8;            // a1/a3 row
    const float x00 = xs[r0l * 3], x01 = xs[r0l * 3 + 1], x02 = xs[r0l * 3 + 2];
    const float x10 = xs[r1l * 3], x11 = xs[r1l * 3 + 1], x12 = xs[r1l * 3 + 2];

    // A fragments: aA[ks][0..3]
    uint32_t aA[4][4];
#pragma unroll
    for (int ks = 0; ks < 4; ks++) {
        int kb = 16 * ks + 2 * tig;
#pragma unroll
        for (int half8 = 0; half8 < 2; half8++) {
            int k = kb + 8 * half8;
            float u00 = fmaf(x02, wcs[128 + k],     fmaf(x01, wcs[64 + k],     fmaf(x00, wcs[k],     bcs[k])));
            float u01 = fmaf(x02, wcs[128 + k + 1], fmaf(x01, wcs[64 + k + 1], fmaf(x00, wcs[k + 1], bcs[k + 1])));
            float u10 = fmaf(x12, wcs[128 + k],     fmaf(x11, wcs[64 + k],     fmaf(x10, wcs[k],     bcs[k])));
            float u11 = fmaf(x12, wcs[128 + k + 1], fmaf(x11, wcs[64 + k + 1], fmaf(x10, wcs[k + 1], bcs[k + 1])));
            aA[ks][0 + 2 * half8] = pack_h2(fmaxf(u00, 0.f), fmaxf(u01, 0.f));
            aA[ks][1 + 2 * half8] = pack_h2(fmaxf(u10, 0.f), fmaxf(u11, 0.f));
        }
    }

    float acc[13][4];
#pragma unroll
    for (int nt = 0; nt < 13; nt++) {
        acc[nt][0] = 0.f; acc[nt][1] = 0.f; acc[nt][2] = 0.f; acc[nt][3] = 0.f;
    }

    const uint2* bf = g_Bfrag;
#pragma unroll
    for (int ks = 0; ks < 4; ks++) {
#pragma unroll
        for (int nt = 0; nt < 13; nt++) {
            uint2 b = __ldg(&bf[(ks * 13 + nt) * 32 + lane]);
            asm volatile(
                "mma.sync.aligned.m16n8k16.row.col.f32.f16.f16.f32 "
                "{%0,%1,%2,%3}, {%4,%5,%6,%7}, {%8,%9}, {%0,%1,%2,%3};"
                : "+f"(acc[nt][0]), "+f"(acc[nt][1]), "+f"(acc[nt][2]), "+f"(acc[nt][3])
                : "r"(aA[ks][0]), "r"(aA[ks][1]), "r"(aA[ks][2]), "r"(aA[ks][3]),
                  "r"(b.x), "r"(b.y));
        }
    }

    // epilogue: D rows gid(+8), cols 8nt + 2tig (+1). Store half2 per row/tile.
    int rem0 = remb + r0l;
    int rem1 = remb + r1l;
    int t0 = rem0 / VV, v0 = rem0 - t0 * VV;
    int t1 = rem1 / VV, v1 = rem1 - t1 * VV;
    __half* zr0 = g_zx_h + (((size_t)(n * VV + v0)) * TT + t0) * G4;
    __half* zr1 = g_zx_h + (((size_t)(n * VV + v1)) * TT + t1) * G4;

#pragma unroll
    for (int nt = 0; nt < 13; nt++) {
        int col = 8 * nt + 2 * tig;
        if (col < 100) {
            *reinterpret_cast<uint32_t*>(&zr0[col]) = pack_h2(acc[nt][0], acc[nt][1]);
            *reinterpret_cast<uint32_t*>(&zr1[col]) = pack_h2(acc[nt][2], acc[nt][3]);
        }
    }
}

// ---------------------------------------------------------------------------
// K2: LSTM recurrence. One warp per (n,v) sequence. f32x2 gate pairs,
// HW tanh.approx, fp16 zx in / fp16 hs out. Bias bl folded into accum init.
// ---------------------------------------------------------------------------
__global__ void __launch_bounds__(32, 12) k2_lstm(const float* __restrict__ U,
                                                  const float* __restrict__ bl) {
    const int l = threadIdx.x & 31;
    const int s = blockIdx.x;
    const int n = s / VV, v = s % VV;
    const int li = (l < 25) ? l : 0;

    ull Uif[25], Ugo[25];
#pragma unroll
    for (int f = 0; f < 25; f++) {
        Uif[f] = pk2(U[f * 100 + li],      U[f * 100 + 25 + li]);
        Ugo[f] = pk2(U[f * 100 + 50 + li], U[f * 100 + 75 + li]);
    }
    const ull blIF = pk2(bl[li],      bl[25 + li]);
    const ull blGO = pk2(bl[50 + li], bl[75 + li]);

    const uint2* zp = reinterpret_cast<const uint2*>(g_zx_h + (size_t)s * TT * G4);
    uint2 z0 = zp[li];
    uint2 z1 = zp[25 + li];

    float c = 0.0f, h = 0.0f;
    __half* hout = g_hs_h + ((size_t)n * TT * VV + v) * FF + li;

    for (int t = 0; t < TT; t++) {
        uint2 zc = z0;
        z0 = z1;
        int tn = (t + 2 < TT) ? (t + 2) : (TT - 1);
        z1 = zp[(size_t)tn * 25 + li];

        ull aIF0 = blIF, aIF1 = 0, aIF2 = 0, aIF3 = 0;
        ull aGO0 = blGO, aGO1 = 0, aGO2 = 0, aGO3 = 0;
#pragma unroll
        for (int f = 0; f < 24; f += 4) {
            float h0 = __shfl_sync(0xffffffffu, h, f);
            float h1 = __shfl_sync(0xffffffffu, h, f + 1);
            float h2 = __shfl_sync(0xffffffffu, h, f + 2);
            float h3 = __shfl_sync(0xffffffffu, h, f + 3);
            ull hh0 = pk2(h0, h0), hh1 = pk2(h1, h1);
            ull hh2 = pk2(h2, h2), hh3 = pk2(h3, h3);
            aIF0 = fma2(hh0, Uif[f],     aIF0); aGO0 = fma2(hh0, Ugo[f],     aGO0);
            aIF1 = fma2(hh1, Uif[f + 1], aIF1); aGO1 = fma2(hh1, Ugo[f + 1], aGO1);
            aIF2 = fma2(hh2, Uif[f + 2], aIF2); aGO2 = fma2(hh2, Ugo[f + 2], aGO2);
            aIF3 = fma2(hh3, Uif[f + 3], aIF3); aGO3 = fma2(hh3, Ugo[f + 3], aGO3);
        }
        {
            float h0 = __shfl_sync(0xffffffffu, h, 24);
            ull hh0 = pk2(h0, h0);
            aIF0 = fma2(hh0, Uif[24], aIF0);
            aGO0 = fma2(hh0, Ugo[24], aGO0);
        }

        __half2 hlo = *reinterpret_cast<__half2*>(&zc.x);
        __half2 hhi = *reinterpret_cast<__half2*>(&zc.y);
        float2 f01 = __half22float2(hlo);
        float2 f23 = __half22float2(hhi);

        ull sIF = add2(add2(aIF0, aIF1), add2(aIF2, aIF3));
        ull sGO = add2(add2(aGO0, aGO1), add2(aGO2, aGO3));
        sIF = add2(sIF, pk2(f01.x, f01.y));
        sGO = add2(sGO, pk2(f23.x, f23.y));

        float gi, gf, gg, go;
        upk2(sIF, gi, gf);
        upk2(sGO, gg, go);

        c = fmaf(hsig(gf), c, hsig(gi) * tanh_fast(gg));
        h = hsig(go) * tanh_fast(c);

        if (l < 25) hout[(size_t)t * (VV * FF)] = __float2half_rn(h);
    }
}

// ---------------------------------------------------------------------------
// K3: block = 160 threads = 2 tiles x 80. (unchanged from 580us baseline)
// ---------------------------------------------------------------------------
__global__ void __launch_bounds__(160) k3_out(const float* __restrict__ x,
                       const float* __restrict__ Wc,
                       const float* __restrict__ bc,
                       const float* __restrict__ bias,
                       float* __restrict__ out) {
    __shared__ float wcs[192];
    __shared__ float bcs[64];
    __shared__ float esr[2][25 * 26];
    __shared__ float xs[2][80];
    __shared__ __align__(16) float x1s[2][25 * 68];
    __shared__ __align__(16) ull es2[2][25 * 26];

    const int tid  = threadIdx.x;
    const int half = (tid >= 80) ? 1 : 0;
    const int t2   = tid - 80 * half;
    const size_t nt = (size_t)blockIdx.x * 2 + half;

    for (int i = tid; i < 192; i += 160) wcs[i] = Wc[i];
    if (tid >= 96 && tid < 160) bcs[tid - 96] = bc[tid - 96];
    if (t2 < 75) xs[half][t2] = x[nt * 75 + t2];

    const __half* hp = g_hs_h + nt * 625;
    for (int idx = t2; idx < 625; idx += 80) {
        float hv = __half2float(hp[idx]);
        float lv = (hv > 0.0f) ? hv : 0.2f * hv;
        esr[half][(idx / 25) * 26 + (idx % 25)] = __expf(lv + __ldg(bias + idx));
    }
    __syncthreads();

    if (t2 < 25) {
        float sum = 0.0f;
#pragma unroll
        for (int w2 = 0; w2 < 25; w2++) sum += esr[half][t2 * 26 + w2];
        float inv = 1.0f / sum;
#pragma unroll
        for (int w2 = 0; w2 < 25; w2++) {
            float e = esr[half][t2 * 26 + w2] * inv;
            es2[half][t2 * 26 + w2] = pk2(e, e);
        }
    }
    for (int idx = t2; idx < 1600; idx += 80) {
        int wj = idx >> 6, cc = idx & 63;
        float u = fmaf(xs[half][wj * 3 + 2], wcs[128 + cc],
                  fmaf(xs[half][wj * 3 + 1], wcs[64 + cc],
                  fmaf(xs[half][wj * 3 + 0], wcs[cc], bcs[cc])));
        x1s[half][wj * 68 + cc] = fmaxf(u, 0.0f);
    }
    __syncthreads();

    {
        const int vg = t2 / 16;
        const int cg = t2 % 16;

        ull a01[5] = {0, 0, 0, 0, 0};
        ull a23[5] = {0, 0, 0, 0, 0};
        const ull* e2 = &es2[half][0];
#pragma unroll
        for (int w2 = 0; w2 < 25; w2++) {
            ulonglong2 xp = *reinterpret_cast<const ulonglong2*>(&x1s[half][w2 * 68 + 4 * cg]);
#pragma unroll
            for (int j = 0; j < 5; j++) {
                ull ee = e2[(vg * 5 + j) * 26 + w2];
                a01[j] = fma2(ee, xp.x, a01[j]);
                a23[j] = fma2(ee, xp.y, a23[j]);
            }
        }

        float* op = out + nt * 1600;
#pragma unroll
        for (int j = 0; j < 5; j++) {
            int vv = vg * 5 + j;
            ulonglong2 o;
            o.x = a01[j];
            o.y = a23[j];
            *reinterpret_cast<ulonglong2*>(&op[vv * 64 + 4 * cg]) = o;
        }
    }
}

extern "C" void kernel_launch(void* const* d_in, const int* in_sizes, int n_in,
                              void* d_out, int out_size) {
    const float* x    = (const float*)d_in[0];
    const float* Wc   = (const float*)d_in[1];
    const float* bc   = (const float*)d_in[2];
    const float* Wl   = (const float*)d_in[3];
    const float* Ul   = (const float*)d_in[4];
    const float* bl   = (const float*)d_in[5];
    const float* bias = (const float*)d_in[6];
    float* out = (float*)d_out;

    k0_prep<<<7, 256>>>(Wl);
    k1_zx_mma<<<12800, 128>>>(x, Wc, bc);
    k2_lstm<<<1600, 32>>>(Ul, bl);
    k3_out<<<16384, 160>>>(x, Wc, bc, bias, out);
}